// round 10
// baseline (speedup 1.0000x reference)
#include <cuda_runtime.h>
#include <cuda_bf16.h>

// CRF NLL: B=512, S=1024, T=64.
// inputs: 0 emissions (B,S,T) f32, 1 tags (B,S) i32, 2 mask (B,S) i32,
//         3 start (T) f32, 4 end (T) f32, 5 transitions (T,T) f32
// output: scalar f32 = -(sum_b ll_b) / (sum_b L_b)
//
// Forward-backward split (Z = alpha_mid . beta_mid), scaled linear domain,
// all-bf16 update path. BOTH chains of one batch (fwd alpha, bwd beta) run
// in ONE warp's instruction stream: each chain's exposed latency is hidden
// by the other's HFMA2 issue. 4 warps/block x 128 blocks = 1 warp/SMSP on
// all 128 SMs. Join is in-warp (no cross-warp sync at all in the hot loop).

#define B_ 512
#define S_ 1024
#define T_ 64
#define FULLMASK 0xffffffffu

__device__ float g_ll[B_];
__device__ float g_len[B_];

typedef __nv_bfloat162 bf2;

__device__ __forceinline__ bf2 bf2pack(float lo, float hi) {
    return __float22bfloat162_rn(make_float2(lo, hi));
}
__device__ __forceinline__ unsigned bf2bits(bf2 v) {
    return *(unsigned*)&v;
}
__device__ __forceinline__ bf2 bits2bf2(unsigned u) {
    bf2 v;
    *(unsigned*)&v = u;
    return v;
}

// 4 warps/block, one batch per warp (both its chains). grid = 128.
__global__ void __launch_bounds__(128) crf_main(
    const float* __restrict__ emis,
    const int* __restrict__ tags,
    const int* __restrict__ mask,
    const float* __restrict__ start,
    const float* __restrict__ endt,
    const float* __restrict__ trans)
{
    __shared__ __align__(16) bf2 sh_w[4][2][2][32];  // [warp][chain][buf][lane]

    const int lane = threadIdx.x & 31;
    const int wid  = threadIdx.x >> 5;
    const int b    = blockIdx.x * 4 + wid;

    const int j0 = 2 * lane;
    const int j1 = j0 + 1;

    const int base = b * S_;
    const float* em = emis + (size_t)base * T_;
    const float2* ep = (const float2*)em;

    // ---- E in bf16: columns j0/j1 (fwd) and rows j0/j1 (bwd) ----
    bf2 Ej0[T_ / 2], Ej1[T_ / 2];   // Ej0[m] = (E[2m][j0], E[2m+1][j0])
    bf2 Ri0[T_ / 2], Ri1[T_ / 2];   // Ri0[m] = (E[j0][2m], E[j0][2m+1])
#pragma unroll
    for (int m = 0; m < T_ / 2; m++) {
        float2 ca = *(const float2*)&trans[(2 * m) * T_ + j0];
        float2 cb = *(const float2*)&trans[(2 * m + 1) * T_ + j0];
        Ej0[m] = bf2pack(__expf(ca.x), __expf(cb.x));
        Ej1[m] = bf2pack(__expf(ca.y), __expf(cb.y));
        float2 ra = *(const float2*)&trans[j0 * T_ + 2 * m];
        float2 rb = *(const float2*)&trans[j1 * T_ + 2 * m];
        Ri0[m] = bf2pack(__expf(ra.x), __expf(ra.y));
        Ri1[m] = bf2pack(__expf(rb.x), __expf(rb.y));
    }

    // ---- sequence length L (prefix mask) ----
    int lp = 0;
#pragma unroll 4
    for (int s = lane; s < S_; s += 32) lp += mask[base + s];
#pragma unroll
    for (int o = 16; o > 0; o >>= 1) lp += __shfl_xor_sync(FULLMASK, lp, o);
    const int L = lp;
    const int mid = L >> 1;

    // ---- numerator (whole sequence, one warp) ----
    float num = 0.0f;
    for (int s = 1 + lane; s < L; s += 32) {
        int tp = tags[base + s - 1];
        int tc = tags[base + s];
        num += trans[tp * T_ + tc] + em[s * T_ + tc];
    }
#pragma unroll
    for (int o = 16; o > 0; o >>= 1) num += __shfl_xor_sync(FULLMASK, num, o);
    if (lane == 0) {
        int tg0 = tags[base];
        int tgl = tags[base + L - 1];
        num += start[tg0] + em[tg0] + endt[tgl];
    }

    // ---- chain inits ----
    // forward: w_0 = exp(start + em_0)
    float2 e0 = ep[lane];
    float w0f = __expf(start[j0] + e0.x);
    float w1f = __expf(start[j1] + e0.y);
    bf2 w2 = bf2pack(w0f, w1f);
    float2 pf1 = ep[1 * 32 + lane];
    float2 pf2 = ep[2 * 32 + lane];

    // backward: u_{L-1} = exp(end) o exp(em[L-1])
    float2 eL = ep[(L - 1) * 32 + lane];
    float u0f = __expf(endt[j0]) * __expf(eL.x);
    float u1f = __expf(endt[j1]) * __expf(eL.y);
    bf2 u2 = bf2pack(u0f, u1f);
    float2 pb1 = ep[(L - 2) * 32 + lane];
    float2 pb2 = ep[(L - 3) * 32 + lane];

    float rF, rB;
    int   kF, kB;
    {
        float wa = __shfl_sync(FULLMASK, w0f, 0);
        float ub = __shfl_sync(FULLMASK, u0f, 0);
        int ka = ((__float_as_int(wa) >> 23) & 0xff) - 127;
        int kb = ((__float_as_int(ub) >> 23) & 0xff) - 127;
        ka = max(-126, min(126, ka));
        kb = max(-126, min(126, kb));
        rF = __int_as_float((127 - ka) << 23); kF = ka;
        rB = __int_as_float((127 - kb) << 23); kB = kb;
    }
    float csF = 0.0f, csB = 0.0f;

    const bf2 z2 = bf2pack(0.0f, 0.0f);

    // fused loop: i-th iter does fwd step s=1+i and bwd step t=L-2-i.
    // fwd runs i=0..mid-1 (alpha_mid after last); bwd active while t>=mid.
    for (int i = 0; i < mid; i++) {
        const int s = 1 + i;
        const int t = L - 2 - i;
        const bool actB = (t >= mid);
        const int pb = i & 1;

        sh_w[wid][0][pb][lane] = w2;
        sh_w[wid][1][pb][lane] = u2;
        __syncwarp();

        // off-chain: emission exps + prefetch, both chains
        float FnF0 = __expf(pf1.x), FnF1 = __expf(pf1.y);
        pf1 = pf2;
        int sp = s + 2; if (sp >= S_) sp = S_ - 1;
        pf2 = ep[sp * 32 + lane];
        bf2 FrF = bf2pack(FnF0 * rF, FnF1 * rF);

        float FnB0 = __expf(pb1.x), FnB1 = __expf(pb1.y);
        pb1 = pb2;
        int tp2 = t - 2; if (tp2 < 0) tp2 = 0;
        pb2 = ep[tp2 * 32 + lane];
        bf2 FrB = (t == mid) ? bf2pack(rB, rB) : bf2pack(FnB0 * rB, FnB1 * rB);

        // ---- forward matvec: v[j] = sum_i w[i] * E[i][j] ----
        const uint4* qF = (const uint4*)sh_w[wid][0][pb];
        bf2 f00 = z2, f01 = z2, f02 = z2, f03 = z2;
        bf2 f10 = z2, f11 = z2, f12 = z2, f13 = z2;
        // ---- backward matvec: v[i] = sum_j E[i][j] * u[j] ----
        const uint4* qB = (const uint4*)sh_w[wid][1][pb];
        bf2 g00 = z2, g01 = z2, g02 = z2, g03 = z2;
        bf2 g10 = z2, g11 = z2, g12 = z2, g13 = z2;
#pragma unroll
        for (int g = 0; g < 8; g++) {
            uint4 vF = qF[g];
            uint4 vB = qB[g];
            bf2 wsF0 = bits2bf2(vF.x), wsF1 = bits2bf2(vF.y);
            bf2 wsF2 = bits2bf2(vF.z), wsF3 = bits2bf2(vF.w);
            bf2 usB0 = bits2bf2(vB.x), usB1 = bits2bf2(vB.y);
            bf2 usB2 = bits2bf2(vB.z), usB3 = bits2bf2(vB.w);
            f00 = __hfma2(wsF0, Ej0[4 * g + 0], f00);
            f01 = __hfma2(wsF1, Ej0[4 * g + 1], f01);
            f02 = __hfma2(wsF2, Ej0[4 * g + 2], f02);
            f03 = __hfma2(wsF3, Ej0[4 * g + 3], f03);
            f10 = __hfma2(wsF0, Ej1[4 * g + 0], f10);
            f11 = __hfma2(wsF1, Ej1[4 * g + 1], f11);
            f12 = __hfma2(wsF2, Ej1[4 * g + 2], f12);
            f13 = __hfma2(wsF3, Ej1[4 * g + 3], f13);
            g00 = __hfma2(usB0, Ri0[4 * g + 0], g00);
            g01 = __hfma2(usB1, Ri0[4 * g + 1], g01);
            g02 = __hfma2(usB2, Ri0[4 * g + 2], g02);
            g03 = __hfma2(usB3, Ri0[4 * g + 3], g03);
            g10 = __hfma2(usB0, Ri1[4 * g + 0], g10);
            g11 = __hfma2(usB1, Ri1[4 * g + 1], g11);
            g12 = __hfma2(usB2, Ri1[4 * g + 2], g12);
            g13 = __hfma2(usB3, Ri1[4 * g + 3], g13);
        }
        // fwd reduce + update
        {
            bf2 s0 = __hadd2(__hadd2(f00, f01), __hadd2(f02, f03));
            bf2 s1 = __hadd2(__hadd2(f10, f11), __hadd2(f12, f13));
            unsigned a0 = bf2bits(s0), a1 = bf2bits(s1);
            bf2 lo2 = bits2bf2(__byte_perm(a0, a1, 0x5410));
            bf2 hi2 = bits2bf2(__byte_perm(a0, a1, 0x7632));
            w2 = __hmul2(__hadd2(lo2, hi2), FrF);
            csF += (float)kF;
        }
        // bwd reduce + predicated update
        {
            bf2 s0 = __hadd2(__hadd2(g00, g01), __hadd2(g02, g03));
            bf2 s1 = __hadd2(__hadd2(g10, g11), __hadd2(g12, g13));
            unsigned a0 = bf2bits(s0), a1 = bf2bits(s1);
            bf2 lo2 = bits2bf2(__byte_perm(a0, a1, 0x5410));
            bf2 hi2 = bits2bf2(__byte_perm(a0, a1, 0x7632));
            bf2 un = __hmul2(__hadd2(lo2, hi2), FrB);
            if (actB) {
                u2 = un;
                csB += (float)kB;
            }
        }

        // resample rescale exponents (shadowed by next iter's matvec)
        unsigned uwF = __shfl_sync(FULLMASK, bf2bits(w2), 0);
        unsigned uwB = __shfl_sync(FULLMASK, bf2bits(u2), 0);
        int ka = (int)((uwF >> 7) & 0xff) - 127;
        int kb = (int)((uwB >> 7) & 0xff) - 127;
        ka = max(-126, min(126, ka));
        kb = max(-126, min(126, kb));
        rF = __int_as_float((127 - ka) << 23); kF = ka;
        rB = __int_as_float((127 - kb) << 23); kB = kb;
    }

    // ---- join (in-warp): Z = sum_i alpha_mid[i] * beta_mid[i] ----
    float2 af = __bfloat1622float2(w2);
    float2 bb = __bfloat1622float2(u2);
    float e = af.x * bb.x + af.y * bb.y;
#pragma unroll
    for (int o = 16; o > 0; o >>= 1) e += __shfl_xor_sync(FULLMASK, e, o);
    if (lane == 0) {
        float den = (float)(((double)csF + (double)csB) * 0.6931471805599453)
                    + __logf(e);
        g_ll[b]  = num - den;
        g_len[b] = (float)L;
    }
}

__global__ void crf_finalize(float* __restrict__ out) {
    __shared__ float s_ll[16];
    __shared__ float s_ln[16];
    int t = threadIdx.x;  // 512 threads
    float ll = g_ll[t];
    float ln = g_len[t];
#pragma unroll
    for (int o = 16; o > 0; o >>= 1) {
        ll += __shfl_xor_sync(FULLMASK, ll, o);
        ln += __shfl_xor_sync(FULLMASK, ln, o);
    }
    int w = t >> 5;
    if ((t & 31) == 0) { s_ll[w] = ll; s_ln[w] = ln; }
    __syncthreads();
    if (t == 0) {
        float sll = 0.0f, sln = 0.0f;
#pragma unroll
        for (int i = 0; i < 16; i++) { sll += s_ll[i]; sln += s_ln[i]; }
        out[0] = -(sll / sln);
    }
}

extern "C" void kernel_launch(void* const* d_in, const int* in_sizes, int n_in,
                              void* d_out, int out_size) {
    const float* emis  = (const float*)d_in[0];
    const int*   tags  = (const int*)d_in[1];
    const int*   mask  = (const int*)d_in[2];
    const float* start = (const float*)d_in[3];
    const float* endt  = (const float*)d_in[4];
    const float* trans = (const float*)d_in[5];
    float* out = (float*)d_out;

    crf_main<<<B_ / 4, 128>>>(emis, tags, mask, start, endt, trans);
    crf_finalize<<<1, B_>>>(out);
}

// round 11
// speedup vs baseline: 1.2070x; 1.2070x over previous
#include <cuda_runtime.h>
#include <cuda_bf16.h>

// CRF NLL: B=512, S=1024, T=64.
// inputs: 0 emissions (B,S,T) f32, 1 tags (B,S) i32, 2 mask (B,S) i32,
//         3 start (T) f32, 4 end (T) f32, 5 transitions (T,T) f32
// output: scalar f32 = -(sum_b ll_b) / (sum_b L_b)
//
// Forward-backward split (Z = alpha_mid . beta_mid), scaled linear domain,
// all-bf16 update path (HFMA2 matvec -> PRMT pair-sum -> HMUL2 by
// Fr2=bf16(exp(em)*2^-k) -> STS.32; rescale k from bf16 exponent bits).
// Grid: 128 blocks x 8 warps = 2 independent chains per SMSP on 128 SMs
// (the R8 shape, which measured chain-bound; the trimmed path shortens
// the chain).

#define B_ 512
#define S_ 1024
#define T_ 64
#define FULLMASK 0xffffffffu

__device__ float g_ll[B_];
__device__ float g_len[B_];

typedef __nv_bfloat162 bf2;

__device__ __forceinline__ bf2 bf2pack(float lo, float hi) {
    return __float22bfloat162_rn(make_float2(lo, hi));
}
__device__ __forceinline__ unsigned bf2bits(bf2 v) {
    return *(unsigned*)&v;
}
__device__ __forceinline__ bf2 bits2bf2(unsigned u) {
    bf2 v;
    *(unsigned*)&v = u;
    return v;
}

// 8 warps/block = 4 batches/block (fwd+bwd warp per batch). grid = 128.
__global__ void __launch_bounds__(256) crf_main(
    const float* __restrict__ emis,
    const int* __restrict__ tags,
    const int* __restrict__ mask,
    const float* __restrict__ start,
    const float* __restrict__ endt,
    const float* __restrict__ trans)
{
    __shared__ __align__(16) bf2 sh_w[8][2][32];     // per-warp exchange (bf16)
    __shared__ __align__(16) float sh_a[4][T_];      // forward's alpha_mid (f32)
    __shared__ float sh_sc[4][2];                    // [pair][{csF, numF}]

    const int lane = threadIdx.x & 31;
    const int wid  = threadIdx.x >> 5;
    const int pair = wid >> 1;      // 0..3
    const int role = wid & 1;       // 0 = forward, 1 = backward
    const int b    = blockIdx.x * 4 + pair;

    const int j0 = 2 * lane;
    const int j1 = j0 + 1;

    const int base = b * S_;
    const float* em = emis + (size_t)base * T_;
    const float2* ep = (const float2*)em;

    // ---- sequence length L (prefix mask) ----
    int lp = 0;
#pragma unroll 4
    for (int s = lane; s < S_; s += 32) lp += mask[base + s];
#pragma unroll
    for (int o = 16; o > 0; o >>= 1) lp += __shfl_xor_sync(FULLMASK, lp, o);
    const int L = lp;
    const int mid = L >> 1;

    if (role == 0) {
        // ================= FORWARD: alpha over s = 0..mid =================
        bf2 Ej0[T_ / 2];
        bf2 Ej1[T_ / 2];
#pragma unroll
        for (int m = 0; m < T_ / 2; m++) {
            float2 ra = *(const float2*)&trans[(2 * m) * T_ + j0];
            float2 rb = *(const float2*)&trans[(2 * m + 1) * T_ + j0];
            Ej0[m] = bf2pack(__expf(ra.x), __expf(rb.x));
            Ej1[m] = bf2pack(__expf(ra.y), __expf(rb.y));
        }

        // numerator over s in [1, mid]
        float num = 0.0f;
        for (int s = 1 + lane; s <= mid; s += 32) {
            int tp = tags[base + s - 1];
            int tc = tags[base + s];
            num += trans[tp * T_ + tc] + em[s * T_ + tc];
        }
#pragma unroll
        for (int o = 16; o > 0; o >>= 1) num += __shfl_xor_sync(FULLMASK, num, o);
        if (lane == 0) {
            int tg0 = tags[base];
            num += start[tg0] + em[tg0];
        }

        // init: w_0 = exp(start + em_0)
        float2 e0 = ep[lane];
        float w0f = __expf(start[j0] + e0.x);
        float w1f = __expf(start[j1] + e0.y);
        bf2 w2 = bf2pack(w0f, w1f);

        float2 p1 = ep[1 * 32 + lane];
        float2 p2 = ep[2 * 32 + lane];

        float r;
        int   kpend;
        {
            float w00 = __shfl_sync(FULLMASK, w0f, 0);
            int k = ((__float_as_int(w00) >> 23) & 0xff) - 127;
            k = max(-126, min(126, k));
            r = __int_as_float((127 - k) << 23);
            kpend = k;
        }
        float csum = 0.0f;

        const bf2 z2 = bf2pack(0.0f, 0.0f);

        for (int s = 1; s <= mid; s++) {
            const int pb = s & 1;
            sh_w[wid][pb][lane] = w2;
            __syncwarp();

            // F_s = exp(em[s]) (p1 holds em[s]); advance prefetch
            float Fn0 = __expf(p1.x);
            float Fn1 = __expf(p1.y);
            p1 = p2;
            int sp = s + 2; if (sp >= S_) sp = S_ - 1;
            p2 = ep[sp * 32 + lane];
            bf2 Fr2 = bf2pack(Fn0 * r, Fn1 * r);  // off-chain vs matvec

            const uint4* q = (const uint4*)sh_w[wid][pb];
            bf2 a00 = z2, a01 = z2, a02 = z2, a03 = z2;    // output j0
            bf2 a10 = z2, a11 = z2, a12 = z2, a13 = z2;    // output j1
#pragma unroll
            for (int g = 0; g < 8; g++) {
                uint4 v = q[g];
                bf2 ws0 = bits2bf2(v.x);
                bf2 ws1 = bits2bf2(v.y);
                bf2 ws2 = bits2bf2(v.z);
                bf2 ws3 = bits2bf2(v.w);
                a00 = __hfma2(ws0, Ej0[4 * g + 0], a00);
                a01 = __hfma2(ws1, Ej0[4 * g + 1], a01);
                a02 = __hfma2(ws2, Ej0[4 * g + 2], a02);
                a03 = __hfma2(ws3, Ej0[4 * g + 3], a03);
                a10 = __hfma2(ws0, Ej1[4 * g + 0], a10);
                a11 = __hfma2(ws1, Ej1[4 * g + 1], a11);
                a12 = __hfma2(ws2, Ej1[4 * g + 2], a12);
                a13 = __hfma2(ws3, Ej1[4 * g + 3], a13);
            }
            bf2 s0 = __hadd2(__hadd2(a00, a01), __hadd2(a02, a03));
            bf2 s1 = __hadd2(__hadd2(a10, a11), __hadd2(a12, a13));
            unsigned u0 = bf2bits(s0), u1 = bf2bits(s1);
            bf2 lo2 = bits2bf2(__byte_perm(u0, u1, 0x5410)); // (s0.lo, s1.lo)
            bf2 hi2 = bits2bf2(__byte_perm(u0, u1, 0x7632)); // (s0.hi, s1.hi)
            w2 = __hmul2(__hadd2(lo2, hi2), Fr2);

            csum += (float)kpend;

            unsigned uw = __shfl_sync(FULLMASK, bf2bits(w2), 0);
            int k = (int)((uw >> 7) & 0xff) - 127;   // bf16 exponent of w[0]
            k = max(-126, min(126, k));
            r = __int_as_float((127 - k) << 23);
            kpend = k;
        }

        // publish alpha_mid (scaled) + scalars
        float2 af = __bfloat1622float2(w2);
        *(float2*)&sh_a[pair][j0] = af;
        if (lane == 0) {
            sh_sc[pair][0] = csum;
            sh_sc[pair][1] = num;
        }
    } else {
        // ================= BACKWARD: beta over s = L-1..mid =================
        bf2 Ri0[T_ / 2];
        bf2 Ri1[T_ / 2];
#pragma unroll
        for (int m = 0; m < T_ / 2; m++) {
            float2 ra = *(const float2*)&trans[j0 * T_ + 2 * m];
            float2 rb = *(const float2*)&trans[j1 * T_ + 2 * m];
            Ri0[m] = bf2pack(__expf(ra.x), __expf(ra.y));
            Ri1[m] = bf2pack(__expf(rb.x), __expf(rb.y));
        }

        // numerator over s in (mid, L)
        float num = 0.0f;
        for (int s = mid + 1 + lane; s < L; s += 32) {
            int tp = tags[base + s - 1];
            int tc = tags[base + s];
            num += trans[tp * T_ + tc] + em[s * T_ + tc];
        }
#pragma unroll
        for (int o = 16; o > 0; o >>= 1) num += __shfl_xor_sync(FULLMASK, num, o);
        if (lane == 0) {
            int tgl = tags[base + L - 1];
            num += endt[tgl];
        }

        // init: u_{L-1} = exp(end) o exp(em[L-1])
        float2 eL = ep[(L - 1) * 32 + lane];
        float u0f = __expf(endt[j0]) * __expf(eL.x);
        float u1f = __expf(endt[j1]) * __expf(eL.y);
        bf2 u2 = bf2pack(u0f, u1f);

        float2 p1 = ep[(L - 2) * 32 + lane];
        float2 p2 = ep[(L - 3) * 32 + lane];

        float r;
        int   kpend;
        {
            float u00 = __shfl_sync(FULLMASK, u0f, 0);
            int k = ((__float_as_int(u00) >> 23) & 0xff) - 127;
            k = max(-126, min(126, k));
            r = __int_as_float((127 - k) << 23);
            kpend = k;
        }
        float csum = 0.0f;

        const bf2 z2 = bf2pack(0.0f, 0.0f);

        for (int t = L - 2; t >= mid; t--) {
            const int pb = t & 1;
            sh_w[wid][pb][lane] = u2;
            __syncwarp();

            // F_t = exp(em[t]) (p1 holds em[t]); advance prefetch
            float Fn0 = __expf(p1.x);
            float Fn1 = __expf(p1.y);
            p1 = p2;
            int tp2 = t - 2; if (tp2 < 0) tp2 = 0;
            p2 = ep[tp2 * 32 + lane];
            // final step (t==mid): produce beta_mid (no emission factor)
            bf2 Fr2 = (t == mid) ? bf2pack(r, r) : bf2pack(Fn0 * r, Fn1 * r);

            // matvec: v[i] = sum_j E[i][j] * u[j]
            const uint4* q = (const uint4*)sh_w[wid][pb];
            bf2 a00 = z2, a01 = z2, a02 = z2, a03 = z2;    // output row j0
            bf2 a10 = z2, a11 = z2, a12 = z2, a13 = z2;    // output row j1
#pragma unroll
            for (int g = 0; g < 8; g++) {
                uint4 v = q[g];
                bf2 us0 = bits2bf2(v.x);
                bf2 us1 = bits2bf2(v.y);
                bf2 us2 = bits2bf2(v.z);
                bf2 us3 = bits2bf2(v.w);
                a00 = __hfma2(us0, Ri0[4 * g + 0], a00);
                a01 = __hfma2(us1, Ri0[4 * g + 1], a01);
                a02 = __hfma2(us2, Ri0[4 * g + 2], a02);
                a03 = __hfma2(us3, Ri0[4 * g + 3], a03);
                a10 = __hfma2(us0, Ri1[4 * g + 0], a10);
                a11 = __hfma2(us1, Ri1[4 * g + 1], a11);
                a12 = __hfma2(us2, Ri1[4 * g + 2], a12);
                a13 = __hfma2(us3, Ri1[4 * g + 3], a13);
            }
            bf2 s0 = __hadd2(__hadd2(a00, a01), __hadd2(a02, a03));
            bf2 s1 = __hadd2(__hadd2(a10, a11), __hadd2(a12, a13));
            unsigned v0 = bf2bits(s0), v1 = bf2bits(s1);
            bf2 lo2 = bits2bf2(__byte_perm(v0, v1, 0x5410));
            bf2 hi2 = bits2bf2(__byte_perm(v0, v1, 0x7632));
            u2 = __hmul2(__hadd2(lo2, hi2), Fr2);

            csum += (float)kpend;

            unsigned uw = __shfl_sync(FULLMASK, bf2bits(u2), 0);
            int k = (int)((uw >> 7) & 0xff) - 127;
            k = max(-126, min(126, k));
            r = __int_as_float((127 - k) << 23);
            kpend = k;
        }

        __syncthreads();

        // ---- join: Z = sum_i alpha_mid[i] * beta_mid[i] ----
        float2 a = *(const float2*)&sh_a[pair][j0];
        float2 bb = __bfloat1622float2(u2);   // beta_mid (scaled)
        float e = a.x * bb.x + a.y * bb.y;
#pragma unroll
        for (int o = 16; o > 0; o >>= 1) e += __shfl_xor_sync(FULLMASK, e, o);
        if (lane == 0) {
            float csF  = sh_sc[pair][0];
            float numF = sh_sc[pair][1];
            float den = (float)(((double)csF + (double)csum) * 0.6931471805599453)
                        + __logf(e);
            g_ll[b]  = (numF + num) - den;
            g_len[b] = (float)L;
        }
        return;
    }
    // forward warps arrive here
    __syncthreads();
}

__global__ void crf_finalize(float* __restrict__ out) {
    __shared__ float s_ll[16];
    __shared__ float s_ln[16];
    int t = threadIdx.x;  // 512 threads
    float ll = g_ll[t];
    float ln = g_len[t];
#pragma unroll
    for (int o = 16; o > 0; o >>= 1) {
        ll += __shfl_xor_sync(FULLMASK, ll, o);
        ln += __shfl_xor_sync(FULLMASK, ln, o);
    }
    int w = t >> 5;
    if ((t & 31) == 0) { s_ll[w] = ll; s_ln[w] = ln; }
    __syncthreads();
    if (t == 0) {
        float sll = 0.0f, sln = 0.0f;
#pragma unroll
        for (int i = 0; i < 16; i++) { sll += s_ll[i]; sln += s_ln[i]; }
        out[0] = -(sll / sln);
    }
}

extern "C" void kernel_launch(void* const* d_in, const int* in_sizes, int n_in,
                              void* d_out, int out_size) {
    const float* emis  = (const float*)d_in[0];
    const int*   tags  = (const int*)d_in[1];
    const int*   mask  = (const int*)d_in[2];
    const float* start = (const float*)d_in[3];
    const float* endt  = (const float*)d_in[4];
    const float* trans = (const float*)d_in[5];
    float* out = (float*)d_out;

    crf_main<<<B_ / 4, 256>>>(emis, tags, mask, start, endt, trans);
    crf_finalize<<<1, B_>>>(out);
}

// round 12
// speedup vs baseline: 1.4292x; 1.1841x over previous
#include <cuda_runtime.h>
#include <cuda_bf16.h>

// CRF NLL: B=512, S=1024, T=64.
// inputs: 0 emissions (B,S,T) f32, 1 tags (B,S) i32, 2 mask (B,S) i32,
//         3 start (T) f32, 4 end (T) f32, 5 transitions (T,T) f32
// output: scalar f32 = -(sum_b ll_b) / (sum_b L_b)
//
// Forward-backward split (Z = alpha_mid . beta_mid), scaled linear domain.
// The w-vector all-gather is done with SHFL.IDX (w fits in one 32-bit reg
// per lane as bf16x2) — no smem, no syncwarp in the hot loop. The g=0
// shuffle doubles as the rescale-exponent sample (k(w_{s-1}) applied at
// step s: stable frac recurrence). bf16 HFMA2 matvec, depth-4 accumulator
// chains, f32 commit (R8's proven path), emission exp one iteration ahead
// + 3-deep load queue. 8 warps/block x 128 blocks = 2 chains per SMSP.

#define B_ 512
#define S_ 1024
#define T_ 64
#define FULLMASK 0xffffffffu

__device__ float g_ll[B_];
__device__ float g_len[B_];

typedef __nv_bfloat162 bf2;

__device__ __forceinline__ bf2 bf2pack(float lo, float hi) {
    return __float22bfloat162_rn(make_float2(lo, hi));
}
__device__ __forceinline__ unsigned bf2bits(bf2 v) {
    return *(unsigned*)&v;
}
__device__ __forceinline__ bf2 bits2bf2(unsigned u) {
    bf2 v;
    *(unsigned*)&v = u;
    return v;
}

// 8 warps/block = 4 batches/block (fwd+bwd warp per batch). grid = 128.
__global__ void __launch_bounds__(256) crf_main(
    const float* __restrict__ emis,
    const int* __restrict__ tags,
    const int* __restrict__ mask,
    const float* __restrict__ start,
    const float* __restrict__ endt,
    const float* __restrict__ trans)
{
    __shared__ __align__(16) float sh_a[4][T_];      // forward's alpha_mid (f32)
    __shared__ float sh_sc[4][2];                    // [pair][{csF, numF}]

    const int lane = threadIdx.x & 31;
    const int wid  = threadIdx.x >> 5;
    const int pair = wid >> 1;      // 0..3
    const int role = wid & 1;       // 0 = forward, 1 = backward
    const int b    = blockIdx.x * 4 + pair;

    const int j0 = 2 * lane;
    const int j1 = j0 + 1;

    const int base = b * S_;
    const float* em = emis + (size_t)base * T_;
    const float2* ep = (const float2*)em;

    // ---- sequence length L (prefix mask) ----
    int lp = 0;
#pragma unroll 4
    for (int s = lane; s < S_; s += 32) lp += mask[base + s];
#pragma unroll
    for (int o = 16; o > 0; o >>= 1) lp += __shfl_xor_sync(FULLMASK, lp, o);
    const int L = lp;           // in [512, 1024]
    const int mid = L >> 1;     // >= 256

    const bf2 z2 = bf2pack(0.0f, 0.0f);

    if (role == 0) {
        // ================= FORWARD: alpha over s = 0..mid =================
        // Ej0[g] = bf16(E[2g][j0], E[2g+1][j0]); Ej1 likewise for col j1.
        bf2 Ej0[T_ / 2];
        bf2 Ej1[T_ / 2];
#pragma unroll
        for (int m = 0; m < T_ / 2; m++) {
            float2 ra = *(const float2*)&trans[(2 * m) * T_ + j0];
            float2 rb = *(const float2*)&trans[(2 * m + 1) * T_ + j0];
            Ej0[m] = bf2pack(__expf(ra.x), __expf(rb.x));
            Ej1[m] = bf2pack(__expf(ra.y), __expf(rb.y));
        }

        // numerator over s in [1, mid]
        float num = 0.0f;
        for (int s = 1 + lane; s <= mid; s += 32) {
            int tp = tags[base + s - 1];
            int tc = tags[base + s];
            num += trans[tp * T_ + tc] + em[s * T_ + tc];
        }
#pragma unroll
        for (int o = 16; o > 0; o >>= 1) num += __shfl_xor_sync(FULLMASK, num, o);
        if (lane == 0) {
            int tg0 = tags[base];
            num += start[tg0] + em[tg0];
        }

        // init: w_0 = exp(start + em_0)
        float2 e0 = ep[lane];
        float w0f = __expf(start[j0] + e0.x);
        float w1f = __expf(start[j1] + e0.y);
        bf2 w2 = bf2pack(w0f, w1f);

        // F one iteration ahead + 3-deep load queue.
        // entering iter s: F0/F1 = exp(em[s]); q1=em[s+1], q2=em[s+2], q3=em[s+3]
        float2 q1 = ep[1 * 32 + lane];
        float2 q2 = ep[2 * 32 + lane];
        float2 q3 = ep[3 * 32 + lane];
        float F0 = __expf(q1.x);
        float F1 = __expf(q1.y);
        q1 = q2; q2 = q3;
        q3 = ep[4 * 32 + lane];

        float csum = 0.0f;

        for (int s = 1; s <= mid; s++) {
            unsigned wu = bf2bits(w2);   // w_{s-1}, one reg per lane

            // gather lane0 first: doubles as rescale sample k(w_{s-1})
            unsigned uw0 = __shfl_sync(FULLMASK, wu, 0);
            int k = (int)((uw0 >> 7) & 0xff) - 127;   // bf16 exponent, low half
            k = max(-126, min(126, k));
            float r = __int_as_float((127 - k) << 23);

            // off-chain: next F, advance load queue (load em[s+4])
            float Fn0 = __expf(q1.x);
            float Fn1 = __expf(q1.y);
            q1 = q2; q2 = q3;
            q3 = ep[(s + 4) * 32 + lane];   // s+4 <= mid+4 <= 516 < S_

            // matvec via shfl all-gather: v[j] = sum_i w[i] * E[i][j]
            bf2 A0[8], A1[8];
#pragma unroll
            for (int a = 0; a < 8; a++) { A0[a] = z2; A1[a] = z2; }
            {
                bf2 ws = bits2bf2(uw0);
                A0[0] = __hfma2(ws, Ej0[0], A0[0]);
                A1[0] = __hfma2(ws, Ej1[0], A1[0]);
            }
#pragma unroll
            for (int g = 1; g < 32; g++) {
                bf2 ws = bits2bf2(__shfl_sync(FULLMASK, wu, g));
                A0[g & 7] = __hfma2(ws, Ej0[g], A0[g & 7]);
                A1[g & 7] = __hfma2(ws, Ej1[g], A1[g & 7]);
            }
            bf2 t0 = __hadd2(__hadd2(__hadd2(A0[0], A0[1]), __hadd2(A0[2], A0[3])),
                             __hadd2(__hadd2(A0[4], A0[5]), __hadd2(A0[6], A0[7])));
            bf2 t1 = __hadd2(__hadd2(__hadd2(A1[0], A1[1]), __hadd2(A1[2], A1[3])),
                             __hadd2(__hadd2(A1[4], A1[5]), __hadd2(A1[6], A1[7])));
            float2 f0 = __bfloat1622float2(t0);
            float2 f1 = __bfloat1622float2(t1);

            // commit (f32): w_s = sum * exp(em[s]) * 2^-k
            w0f = (f0.x + f0.y) * (F0 * r);
            w1f = (f1.x + f1.y) * (F1 * r);
            w2 = bf2pack(w0f, w1f);
            csum += (float)k;

            F0 = Fn0;
            F1 = Fn1;
        }

        // publish alpha_mid (scaled, f32) + scalars
        *(float2*)&sh_a[pair][j0] = make_float2(w0f, w1f);
        if (lane == 0) {
            sh_sc[pair][0] = csum;
            sh_sc[pair][1] = num;
        }
    } else {
        // ================= BACKWARD: beta over s = L-1..mid =================
        // Ri0[g] = bf16(E[j0][2g], E[j0][2g+1]); Ri1 likewise for row j1.
        bf2 Ri0[T_ / 2];
        bf2 Ri1[T_ / 2];
#pragma unroll
        for (int m = 0; m < T_ / 2; m++) {
            float2 ra = *(const float2*)&trans[j0 * T_ + 2 * m];
            float2 rb = *(const float2*)&trans[j1 * T_ + 2 * m];
            Ri0[m] = bf2pack(__expf(ra.x), __expf(ra.y));
            Ri1[m] = bf2pack(__expf(rb.x), __expf(rb.y));
        }

        // numerator over s in (mid, L)
        float num = 0.0f;
        for (int s = mid + 1 + lane; s < L; s += 32) {
            int tp = tags[base + s - 1];
            int tc = tags[base + s];
            num += trans[tp * T_ + tc] + em[s * T_ + tc];
        }
#pragma unroll
        for (int o = 16; o > 0; o >>= 1) num += __shfl_xor_sync(FULLMASK, num, o);
        if (lane == 0) {
            int tgl = tags[base + L - 1];
            num += endt[tgl];
        }

        // init: u_{L-1} = exp(end) o exp(em[L-1])  (exchange value)
        float2 eL = ep[(L - 1) * 32 + lane];
        float b0f = __expf(endt[j0]);
        float b1f = __expf(endt[j1]);
        bf2 u2 = bf2pack(b0f * __expf(eL.x), b1f * __expf(eL.y));

        // entering iter t: F0/F1 = exp(em[t]); q1=em[t-1], q2=em[t-2], q3=em[t-3]
        float2 q1 = ep[(L - 2) * 32 + lane];
        float2 q2 = ep[(L - 3) * 32 + lane];
        float2 q3 = ep[(L - 4) * 32 + lane];
        float F0 = __expf(q1.x);
        float F1 = __expf(q1.y);
        q1 = q2; q2 = q3;
        q3 = ep[(L - 5) * 32 + lane];   // L >= 512 -> safe

        float csum = 0.0f;

        for (int t = L - 2; t >= mid; t--) {
            unsigned uu = bf2bits(u2);   // u_{t+1} = beta_{t+1} o F_{t+1}

            unsigned uw0 = __shfl_sync(FULLMASK, uu, 0);
            int k = (int)((uw0 >> 7) & 0xff) - 127;
            k = max(-126, min(126, k));
            float r = __int_as_float((127 - k) << 23);

            // off-chain: next F (= exp(em[t-1])), advance queue (load em[t-4])
            float Fn0 = __expf(q1.x);
            float Fn1 = __expf(q1.y);
            q1 = q2; q2 = q3;
            int tl = t - 4; if (tl < 0) tl = 0;   // t >= mid >= 256: never taken
            q3 = ep[tl * 32 + lane];

            // matvec: v[i] = sum_j E[i][j] * u[j]
            bf2 A0[8], A1[8];
#pragma unroll
            for (int a = 0; a < 8; a++) { A0[a] = z2; A1[a] = z2; }
            {
                bf2 us = bits2bf2(uw0);
                A0[0] = __hfma2(us, Ri0[0], A0[0]);
                A1[0] = __hfma2(us, Ri1[0], A1[0]);
            }
#pragma unroll
            for (int g = 1; g < 32; g++) {
                bf2 us = bits2bf2(__shfl_sync(FULLMASK, uu, g));
                A0[g & 7] = __hfma2(us, Ri0[g], A0[g & 7]);
                A1[g & 7] = __hfma2(us, Ri1[g], A1[g & 7]);
            }
            bf2 t0 = __hadd2(__hadd2(__hadd2(A0[0], A0[1]), __hadd2(A0[2], A0[3])),
                             __hadd2(__hadd2(A0[4], A0[5]), __hadd2(A0[6], A0[7])));
            bf2 t1 = __hadd2(__hadd2(__hadd2(A1[0], A1[1]), __hadd2(A1[2], A1[3])),
                             __hadd2(__hadd2(A1[4], A1[5]), __hadd2(A1[6], A1[7])));
            float2 f0 = __bfloat1622float2(t0);
            float2 f1 = __bfloat1622float2(t1);

            // commit (f32): beta_t = sum * 2^-k; exchange u_t = beta_t o exp(em[t])
            b0f = (f0.x + f0.y) * r;
            b1f = (f1.x + f1.y) * r;
            u2 = bf2pack(b0f * F0, b1f * F1);
            csum += (float)k;

            F0 = Fn0;
            F1 = Fn1;
        }

        __syncthreads();

        // ---- join: Z = sum_i alpha_mid[i] * beta_mid[i] ----
        float2 a = *(const float2*)&sh_a[pair][j0];
        float e = a.x * b0f + a.y * b1f;
#pragma unroll
        for (int o = 16; o > 0; o >>= 1) e += __shfl_xor_sync(FULLMASK, e, o);
        if (lane == 0) {
            float csF  = sh_sc[pair][0];
            float numF = sh_sc[pair][1];
            float den = (float)(((double)csF + (double)csum) * 0.6931471805599453)
                        + __logf(e);
            g_ll[b]  = (numF + num) - den;
            g_len[b] = (float)L;
        }
        return;
    }
    // forward warps arrive here
    __syncthreads();
}

__global__ void crf_finalize(float* __restrict__ out) {
    __shared__ float s_ll[16];
    __shared__ float s_ln[16];
    int t = threadIdx.x;  // 512 threads
    float ll = g_ll[t];
    float ln = g_len[t];
#pragma unroll
    for (int o = 16; o > 0; o >>= 1) {
        ll += __shfl_xor_sync(FULLMASK, ll, o);
        ln += __shfl_xor_sync(FULLMASK, ln, o);
    }
    int w = t >> 5;
    if ((t & 31) == 0) { s_ll[w] = ll; s_ln[w] = ln; }
    __syncthreads();
    if (t == 0) {
        float sll = 0.0f, sln = 0.0f;
#pragma unroll
        for (int i = 0; i < 16; i++) { sll += s_ll[i]; sln += s_ln[i]; }
        out[0] = -(sll / sln);
    }
}

extern "C" void kernel_launch(void* const* d_in, const int* in_sizes, int n_in,
                              void* d_out, int out_size) {
    const float* emis  = (const float*)d_in[0];
    const int*   tags  = (const int*)d_in[1];
    const int*   mask  = (const int*)d_in[2];
    const float* start = (const float*)d_in[3];
    const float* endt  = (const float*)d_in[4];
    const float* trans = (const float*)d_in[5];
    float* out = (float*)d_out;

    crf_main<<<B_ / 4, 256>>>(emis, tags, mask, start, endt, trans);
    crf_finalize<<<1, B_>>>(out);
}

// round 13
// speedup vs baseline: 1.4734x; 1.0310x over previous
#include <cuda_runtime.h>
#include <cuda_bf16.h>

// CRF NLL: B=512, S=1024, T=64.
// inputs: 0 emissions (B,S,T) f32, 1 tags (B,S) i32, 2 mask (B,S) i32,
//         3 start (T) f32, 4 end (T) f32, 5 transitions (T,T) f32
// output: scalar f32 = -(sum_b ll_b) / (sum_b L_b)
//
// Forward-backward split (Z = alpha_mid . beta_mid), scaled linear domain.
// The w-vector all-gather is done with SHFL.IDX (w fits in one 32-bit reg
// per lane as bf16x2) — no smem, no syncwarp in the hot loop. The g=0
// shuffle doubles as the rescale-exponent sample (k(w_{s-1}) applied at
// step s: stable frac recurrence). bf16 HFMA2 matvec, depth-4 accumulator
// chains, f32 commit (R8's proven path), emission exp one iteration ahead
// + 3-deep load queue. 8 warps/block x 128 blocks = 2 chains per SMSP.

#define B_ 512
#define S_ 1024
#define T_ 64
#define FULLMASK 0xffffffffu

__device__ float g_ll[B_];
__device__ float g_len[B_];

typedef __nv_bfloat162 bf2;

__device__ __forceinline__ bf2 bf2pack(float lo, float hi) {
    return __float22bfloat162_rn(make_float2(lo, hi));
}
__device__ __forceinline__ unsigned bf2bits(bf2 v) {
    return *(unsigned*)&v;
}
__device__ __forceinline__ bf2 bits2bf2(unsigned u) {
    bf2 v;
    *(unsigned*)&v = u;
    return v;
}

// 8 warps/block = 4 batches/block (fwd+bwd warp per batch). grid = 128.
__global__ void __launch_bounds__(256) crf_main(
    const float* __restrict__ emis,
    const int* __restrict__ tags,
    const int* __restrict__ mask,
    const float* __restrict__ start,
    const float* __restrict__ endt,
    const float* __restrict__ trans)
{
    __shared__ __align__(16) float sh_a[4][T_];      // forward's alpha_mid (f32)
    __shared__ float sh_sc[4][2];                    // [pair][{csF, numF}]

    const int lane = threadIdx.x & 31;
    const int wid  = threadIdx.x >> 5;
    const int pair = wid >> 1;      // 0..3
    const int role = wid & 1;       // 0 = forward, 1 = backward
    const int b    = blockIdx.x * 4 + pair;

    const int j0 = 2 * lane;
    const int j1 = j0 + 1;

    const int base = b * S_;
    const float* em = emis + (size_t)base * T_;
    const float2* ep = (const float2*)em;

    // ---- sequence length L (prefix mask) ----
    int lp = 0;
#pragma unroll 4
    for (int s = lane; s < S_; s += 32) lp += mask[base + s];
#pragma unroll
    for (int o = 16; o > 0; o >>= 1) lp += __shfl_xor_sync(FULLMASK, lp, o);
    const int L = lp;           // in [512, 1024]
    const int mid = L >> 1;     // >= 256

    const bf2 z2 = bf2pack(0.0f, 0.0f);

    if (role == 0) {
        // ================= FORWARD: alpha over s = 0..mid =================
        // Ej0[g] = bf16(E[2g][j0], E[2g+1][j0]); Ej1 likewise for col j1.
        bf2 Ej0[T_ / 2];
        bf2 Ej1[T_ / 2];
#pragma unroll
        for (int m = 0; m < T_ / 2; m++) {
            float2 ra = *(const float2*)&trans[(2 * m) * T_ + j0];
            float2 rb = *(const float2*)&trans[(2 * m + 1) * T_ + j0];
            Ej0[m] = bf2pack(__expf(ra.x), __expf(rb.x));
            Ej1[m] = bf2pack(__expf(ra.y), __expf(rb.y));
        }

        // numerator over s in [1, mid]
        float num = 0.0f;
        for (int s = 1 + lane; s <= mid; s += 32) {
            int tp = tags[base + s - 1];
            int tc = tags[base + s];
            num += trans[tp * T_ + tc] + em[s * T_ + tc];
        }
#pragma unroll
        for (int o = 16; o > 0; o >>= 1) num += __shfl_xor_sync(FULLMASK, num, o);
        if (lane == 0) {
            int tg0 = tags[base];
            num += start[tg0] + em[tg0];
        }

        // init: w_0 = exp(start + em_0)
        float2 e0 = ep[lane];
        float w0f = __expf(start[j0] + e0.x);
        float w1f = __expf(start[j1] + e0.y);
        bf2 w2 = bf2pack(w0f, w1f);

        // F one iteration ahead + 3-deep load queue.
        // entering iter s: F0/F1 = exp(em[s]); q1=em[s+1], q2=em[s+2], q3=em[s+3]
        float2 q1 = ep[1 * 32 + lane];
        float2 q2 = ep[2 * 32 + lane];
        float2 q3 = ep[3 * 32 + lane];
        float F0 = __expf(q1.x);
        float F1 = __expf(q1.y);
        q1 = q2; q2 = q3;
        q3 = ep[4 * 32 + lane];

        float csum = 0.0f;

        for (int s = 1; s <= mid; s++) {
            unsigned wu = bf2bits(w2);   // w_{s-1}, one reg per lane

            // gather lane0 first: doubles as rescale sample k(w_{s-1})
            unsigned uw0 = __shfl_sync(FULLMASK, wu, 0);
            int k = (int)((uw0 >> 7) & 0xff) - 127;   // bf16 exponent, low half
            k = max(-126, min(126, k));
            float r = __int_as_float((127 - k) << 23);

            // off-chain: next F, advance load queue (load em[s+4])
            float Fn0 = __expf(q1.x);
            float Fn1 = __expf(q1.y);
            q1 = q2; q2 = q3;
            q3 = ep[(s + 4) * 32 + lane];   // s+4 <= mid+4 <= 516 < S_

            // matvec via shfl all-gather: v[j] = sum_i w[i] * E[i][j]
            bf2 A0[8], A1[8];
#pragma unroll
            for (int a = 0; a < 8; a++) { A0[a] = z2; A1[a] = z2; }
            {
                bf2 ws = bits2bf2(uw0);
                A0[0] = __hfma2(ws, Ej0[0], A0[0]);
                A1[0] = __hfma2(ws, Ej1[0], A1[0]);
            }
#pragma unroll
            for (int g = 1; g < 32; g++) {
                bf2 ws = bits2bf2(__shfl_sync(FULLMASK, wu, g));
                A0[g & 7] = __hfma2(ws, Ej0[g], A0[g & 7]);
                A1[g & 7] = __hfma2(ws, Ej1[g], A1[g & 7]);
            }
            bf2 t0 = __hadd2(__hadd2(__hadd2(A0[0], A0[1]), __hadd2(A0[2], A0[3])),
                             __hadd2(__hadd2(A0[4], A0[5]), __hadd2(A0[6], A0[7])));
            bf2 t1 = __hadd2(__hadd2(__hadd2(A1[0], A1[1]), __hadd2(A1[2], A1[3])),
                             __hadd2(__hadd2(A1[4], A1[5]), __hadd2(A1[6], A1[7])));
            float2 f0 = __bfloat1622float2(t0);
            float2 f1 = __bfloat1622float2(t1);

            // commit (f32): w_s = sum * exp(em[s]) * 2^-k
            w0f = (f0.x + f0.y) * (F0 * r);
            w1f = (f1.x + f1.y) * (F1 * r);
            w2 = bf2pack(w0f, w1f);
            csum += (float)k;

            F0 = Fn0;
            F1 = Fn1;
        }

        // publish alpha_mid (scaled, f32) + scalars
        *(float2*)&sh_a[pair][j0] = make_float2(w0f, w1f);
        if (lane == 0) {
            sh_sc[pair][0] = csum;
            sh_sc[pair][1] = num;
        }
    } else {
        // ================= BACKWARD: beta over s = L-1..mid =================
        // Ri0[g] = bf16(E[j0][2g], E[j0][2g+1]); Ri1 likewise for row j1.
        bf2 Ri0[T_ / 2];
        bf2 Ri1[T_ / 2];
#pragma unroll
        for (int m = 0; m < T_ / 2; m++) {
            float2 ra = *(const float2*)&trans[j0 * T_ + 2 * m];
            float2 rb = *(const float2*)&trans[j1 * T_ + 2 * m];
            Ri0[m] = bf2pack(__expf(ra.x), __expf(ra.y));
            Ri1[m] = bf2pack(__expf(rb.x), __expf(rb.y));
        }

        // numerator over s in (mid, L)
        float num = 0.0f;
        for (int s = mid + 1 + lane; s < L; s += 32) {
            int tp = tags[base + s - 1];
            int tc = tags[base + s];
            num += trans[tp * T_ + tc] + em[s * T_ + tc];
        }
#pragma unroll
        for (int o = 16; o > 0; o >>= 1) num += __shfl_xor_sync(FULLMASK, num, o);
        if (lane == 0) {
            int tgl = tags[base + L - 1];
            num += endt[tgl];
        }

        // init: u_{L-1} = exp(end) o exp(em[L-1])  (exchange value)
        float2 eL = ep[(L - 1) * 32 + lane];
        float b0f = __expf(endt[j0]);
        float b1f = __expf(endt[j1]);
        bf2 u2 = bf2pack(b0f * __expf(eL.x), b1f * __expf(eL.y));

        // entering iter t: F0/F1 = exp(em[t]); q1=em[t-1], q2=em[t-2], q3=em[t-3]
        float2 q1 = ep[(L - 2) * 32 + lane];
        float2 q2 = ep[(L - 3) * 32 + lane];
        float2 q3 = ep[(L - 4) * 32 + lane];
        float F0 = __expf(q1.x);
        float F1 = __expf(q1.y);
        q1 = q2; q2 = q3;
        q3 = ep[(L - 5) * 32 + lane];   // L >= 512 -> safe

        float csum = 0.0f;

        for (int t = L - 2; t >= mid; t--) {
            unsigned uu = bf2bits(u2);   // u_{t+1} = beta_{t+1} o F_{t+1}

            unsigned uw0 = __shfl_sync(FULLMASK, uu, 0);
            int k = (int)((uw0 >> 7) & 0xff) - 127;
            k = max(-126, min(126, k));
            float r = __int_as_float((127 - k) << 23);

            // off-chain: next F (= exp(em[t-1])), advance queue (load em[t-4])
            float Fn0 = __expf(q1.x);
            float Fn1 = __expf(q1.y);
            q1 = q2; q2 = q3;
            int tl = t - 4; if (tl < 0) tl = 0;   // t >= mid >= 256: never taken
            q3 = ep[tl * 32 + lane];

            // matvec: v[i] = sum_j E[i][j] * u[j]
            bf2 A0[8], A1[8];
#pragma unroll
            for (int a = 0; a < 8; a++) { A0[a] = z2; A1[a] = z2; }
            {
                bf2 us = bits2bf2(uw0);
                A0[0] = __hfma2(us, Ri0[0], A0[0]);
                A1[0] = __hfma2(us, Ri1[0], A1[0]);
            }
#pragma unroll
            for (int g = 1; g < 32; g++) {
                bf2 us = bits2bf2(__shfl_sync(FULLMASK, uu, g));
                A0[g & 7] = __hfma2(us, Ri0[g], A0[g & 7]);
                A1[g & 7] = __hfma2(us, Ri1[g], A1[g & 7]);
            }
            bf2 t0 = __hadd2(__hadd2(__hadd2(A0[0], A0[1]), __hadd2(A0[2], A0[3])),
                             __hadd2(__hadd2(A0[4], A0[5]), __hadd2(A0[6], A0[7])));
            bf2 t1 = __hadd2(__hadd2(__hadd2(A1[0], A1[1]), __hadd2(A1[2], A1[3])),
                             __hadd2(__hadd2(A1[4], A1[5]), __hadd2(A1[6], A1[7])));
            float2 f0 = __bfloat1622float2(t0);
            float2 f1 = __bfloat1622float2(t1);

            // commit (f32): beta_t = sum * 2^-k; exchange u_t = beta_t o exp(em[t])
            b0f = (f0.x + f0.y) * r;
            b1f = (f1.x + f1.y) * r;
            u2 = bf2pack(b0f * F0, b1f * F1);
            csum += (float)k;

            F0 = Fn0;
            F1 = Fn1;
        }

        __syncthreads();

        // ---- join: Z = sum_i alpha_mid[i] * beta_mid[i] ----
        float2 a = *(const float2*)&sh_a[pair][j0];
        float e = a.x * b0f + a.y * b1f;
#pragma unroll
        for (int o = 16; o > 0; o >>= 1) e += __shfl_xor_sync(FULLMASK, e, o);
        if (lane == 0) {
            float csF  = sh_sc[pair][0];
            float numF = sh_sc[pair][1];
            float den = (float)(((double)csF + (double)csum) * 0.6931471805599453)
                        + __logf(e);
            g_ll[b]  = (numF + num) - den;
            g_len[b] = (float)L;
        }
        return;
    }
    // forward warps arrive here
    __syncthreads();
}

__global__ void crf_finalize(float* __restrict__ out) {
    __shared__ float s_ll[16];
    __shared__ float s_ln[16];
    int t = threadIdx.x;  // 512 threads
    float ll = g_ll[t];
    float ln = g_len[t];
#pragma unroll
    for (int o = 16; o > 0; o >>= 1) {
        ll += __shfl_xor_sync(FULLMASK, ll, o);
        ln += __shfl_xor_sync(FULLMASK, ln, o);
    }
    int w = t >> 5;
    if ((t & 31) == 0) { s_ll[w] = ll; s_ln[w] = ln; }
    __syncthreads();
    if (t == 0) {
        float sll = 0.0f, sln = 0.0f;
#pragma unroll
        for (int i = 0; i < 16; i++) { sll += s_ll[i]; sln += s_ln[i]; }
        out[0] = -(sll / sln);
    }
}

extern "C" void kernel_launch(void* const* d_in, const int* in_sizes, int n_in,
                              void* d_out, int out_size) {
    const float* emis  = (const float*)d_in[0];
    const int*   tags  = (const int*)d_in[1];
    const int*   mask  = (const int*)d_in[2];
    const float* start = (const float*)d_in[3];
    const float* endt  = (const float*)d_in[4];
    const float* trans = (const float*)d_in[5];
    float* out = (float*)d_out;

    crf_main<<<B_ / 4, 256>>>(emis, tags, mask, start, endt, trans);
    crf_finalize<<<1, B_>>>(out);
}